// round 14
// baseline (speedup 1.0000x reference)
#include <cuda_runtime.h>
#include <cuda_bf16.h>
#include <cuda_fp16.h>
#include <cstdint>

// ============================================================================
// RGCN 2-layer, transform-first. Root GEMM fused as a 9th relation.
// GEMMs: single-pass fp16 mma.sync; CTA tile 256x128 (warp grid 4x2 of 64x64)
// so LDSM traffic hits the HMMA floor. 2-stage cp.async pipeline.
// Messages+root fp16. CSR pull aggregation; CSR build + W2 prep on side stream.
// ============================================================================

#define MAXN 50000
#define MAXE 840000
#define RELS 8

__device__ __half g_Y1[(size_t)MAXN * 2304];   // [N, 8*256 + 256(root)]
__device__ __half g_Y2[(size_t)MAXN * 1152];   // [N, 8*128 + 128(root)]
__device__ int    g_cnt[MAXN * RELS];
__device__ int    g_deg[MAXN];
__device__ int    g_offs[MAXN + 1];
__device__ int    g_cur[MAXN];
__device__ unsigned g_csr[MAXE];

__device__ __half g_x16[(size_t)MAXN * 256];
__device__ __half g_h16[(size_t)MAXN * 256];

__device__ __half g_w1[2304 * 256];            // pre-transposed fp16
__device__ __half g_w2[1152 * 256];

// ---------------------------------------------------------------------------
__device__ __forceinline__ void ldsm4(uint32_t* r, uint32_t addr)
{
    asm volatile("ldmatrix.sync.aligned.m8n8.x4.shared.b16 {%0,%1,%2,%3}, [%4];"
                 : "=r"(r[0]), "=r"(r[1]), "=r"(r[2]), "=r"(r[3]) : "r"(addr));
}

__device__ __forceinline__ void mma_f16(float* c, const uint32_t* a, const uint32_t* b)
{
    asm volatile(
        "mma.sync.aligned.m16n8k16.row.col.f32.f16.f16.f32 "
        "{%0,%1,%2,%3}, {%4,%5,%6,%7}, {%8,%9}, {%0,%1,%2,%3};"
        : "+f"(c[0]), "+f"(c[1]), "+f"(c[2]), "+f"(c[3])
        : "r"(a[0]), "r"(a[1]), "r"(a[2]), "r"(a[3]), "r"(b[0]), "r"(b[1]));
}

#define CP_COMMIT() asm volatile("cp.async.commit_group;" ::: "memory")
#define CP_WAIT1()  asm volatile("cp.async.wait_group 1;" ::: "memory")
#define CP_WAIT0()  asm volatile("cp.async.wait_group 0;" ::: "memory")

__device__ __forceinline__ void cp16(uint32_t dst, const void* src, int sz)
{
    asm volatile("cp.async.ca.shared.global [%0], [%1], 16, %2;"
                 :: "r"(dst), "l"(src), "r"(sz));
}

// ---------------------------------------------------------------------------
// Pipelined GEMM: C[M,T] = A16[M,256] @ W[T,256]^T, fp16 out.
// CTA 256x128, 8 warps (4x2 of 64x64), kc=32, 2-stage cp.async.
// smem/stage: A 256x80B + B 128x80B = 30720 B. Total 60 KB.
// ---------------------------------------------------------------------------
#define A_BYTES 20480
#define STG_BYTES 30720
#define SMEMP (2 * STG_BYTES)

__global__ void __launch_bounds__(256)
gemm_pipe(const __half* __restrict__ A16,
          int M,
          const __half* __restrict__ Bw,
          __half* __restrict__ C, int ldc)
{
    extern __shared__ char smem[];
    uint32_t sb0;
    asm("{ .reg .u64 t; cvta.to.shared.u64 t, %1; cvt.u32.u64 %0, t; }"
        : "=r"(sb0) : "l"(smem));

    const int tid  = threadIdx.x;
    const int wid  = tid >> 5;
    const int lane = tid & 31;
    const int wm   = wid >> 1;      // 0..3  (64-row slice)
    const int wn   = wid & 1;       // 0..1  (64-col slice)
    const int bm   = blockIdx.x * 256;
    const int bn   = blockIdx.y * 128;

    float acc[4][8][4];
#pragma unroll
    for (int i = 0; i < 4; i++)
#pragma unroll
        for (int j = 0; j < 8; j++)
#pragma unroll
            for (int q = 0; q < 4; q++) acc[i][j][q] = 0.f;

    const int q8 = lane >> 3;
    const int lg = lane & 7;

    // stage loader: A 1024 chunks + B 512 chunks of 16B, 6 per thread
    auto load_stage = [&](int stage, int k0) {
        uint32_t sb = sb0 + stage * STG_BYTES;
#pragma unroll
        for (int i = 0; i < 6; i++) {
            int sz = 16;
            if (i < 4) {
                int idx = i * 256 + tid;       // 0..1023
                int row = idx >> 2;
                int seg = (idx & 3) * 8;
                int grow = bm + row;
                if (grow >= M) { grow = 0; sz = 0; }
                cp16(sb + row * 80 + seg * 2,
                     A16 + (size_t)grow * 256 + k0 + seg, sz);
            } else {
                int idx = (i - 4) * 256 + tid; // 0..511
                int row = idx >> 2;
                int seg = (idx & 3) * 8;
                cp16(sb + A_BYTES + row * 80 + seg * 2,
                     Bw + (size_t)(bn + row) * 256 + k0 + seg, sz);
            }
        }
        CP_COMMIT();
    };

    load_stage(0, 0);

    for (int kb = 0; kb < 8; kb++) {
        if (kb < 7) load_stage((kb + 1) & 1, (kb + 1) * 32);
        if (kb < 7) CP_WAIT1(); else CP_WAIT0();
        __syncthreads();

        const uint32_t sb = sb0 + (kb & 1) * STG_BYTES;
        const uint32_t sA_b = sb;
        const uint32_t sBw_b = sb + A_BYTES;

#pragma unroll
        for (int ks = 0; ks < 2; ks++) {
            uint32_t bw[16];
#pragma unroll
            for (int np = 0; np < 4; np++) {
                int nrow = wn * 64 + np * 16 + lg + ((q8 >> 1) ? 8 : 0);
                int bcol = ks * 32 + ((q8 & 1) ? 16 : 0);
                ldsm4(&bw[np * 4], sBw_b + nrow * 80 + bcol);
            }
#pragma unroll
            for (int mt = 0; mt < 4; mt++) {
                int arow = wm * 64 + mt * 16 + lg + ((q8 & 1) ? 8 : 0);
                int acol = ks * 32 + ((q8 >> 1) ? 16 : 0);
                uint32_t ah[4];
                ldsm4(ah, sA_b + arow * 80 + acol);
#pragma unroll
                for (int nt = 0; nt < 8; nt++) mma_f16(acc[mt][nt], ah, &bw[nt * 2]);
            }
        }
        __syncthreads();
    }

    // ---- epilogue (fp16) ----
#pragma unroll
    for (int mt = 0; mt < 4; mt++) {
#pragma unroll
        for (int nt = 0; nt < 8; nt++) {
            int gr0  = bm + wm * 64 + mt * 16 + (lane >> 2);
            int gcol = bn + wn * 64 + nt * 8 + (lane & 3) * 2;
#pragma unroll
            for (int h = 0; h < 2; h++) {
                int gr = gr0 + h * 8;
                if (gr < M) {
                    *(__half2*)(C + (size_t)gr * ldc + gcol) =
                        __floats2half2_rn(acc[mt][nt][h * 2 + 0], acc[mt][nt][h * 2 + 1]);
                }
            }
        }
    }
}

// ---------------------------------------------------------------------------
// Prep kernels
// ---------------------------------------------------------------------------
__global__ void convw_kernel(const float* __restrict__ W,
                             __half* __restrict__ w, int N, int total)
{
    int idx = blockIdx.x * blockDim.x + threadIdx.x;
    if (idx >= total) return;
    int n = idx % N;
    int k = (idx / N) & 255;
    int r = idx / (N * 256);
    w[((size_t)r * N + n) * 256 + k] = __float2half_rn(W[idx]);
}

__global__ void convx_kernel(const float* __restrict__ X,
                             __half* __restrict__ x16, size_t total)
{
    size_t i = (size_t)blockIdx.x * blockDim.x + threadIdx.x;
    if (i >= total) return;
    x16[i] = __float2half_rn(X[i]);
}

// ---------------------------------------------------------------------------
// CSR construction
// ---------------------------------------------------------------------------
__global__ void zero_int_kernel(int* p, int n)
{
    int i = blockIdx.x * blockDim.x + threadIdx.x;
    if (i < n) p[i] = 0;
}

__global__ void count_kernel(const int* __restrict__ ei,
                             const int* __restrict__ et,
                             int* __restrict__ cnt, int E)
{
    int e = blockIdx.x * blockDim.x + threadIdx.x;
    if (e < E) atomicAdd(&cnt[ei[E + e] * RELS + et[e]], 1);
}

__global__ void deg_kernel(const int* __restrict__ cnt, int* __restrict__ deg, int n)
{
    int i = blockIdx.x * blockDim.x + threadIdx.x;
    if (i < n) {
        int s = 0;
#pragma unroll
        for (int r = 0; r < RELS; r++) s += cnt[i * RELS + r];
        deg[i] = s;
    }
}

__global__ void scan_kernel(const int* __restrict__ deg, int* __restrict__ offs, int n)
{
    __shared__ int buf[1024];
    __shared__ int carry;
    const int tid = threadIdx.x;
    if (tid == 0) carry = 0;
    __syncthreads();
    for (int base = 0; base < n; base += 1024) {
        int i = base + tid;
        int v = (i < n) ? deg[i] : 0;
        buf[tid] = v;
        __syncthreads();
        for (int d = 1; d < 1024; d <<= 1) {
            int t = (tid >= d) ? buf[tid - d] : 0;
            __syncthreads();
            buf[tid] += t;
            __syncthreads();
        }
        if (i < n) offs[i] = carry + buf[tid] - v;
        __syncthreads();
        if (tid == 0) carry += buf[1023];
        __syncthreads();
    }
    if (tid == 0) offs[n] = carry;
}

__global__ void fill_kernel(const int* __restrict__ ei,
                            const int* __restrict__ et,
                            const int* __restrict__ offs,
                            int* __restrict__ cur,
                            unsigned* __restrict__ csr, int E)
{
    int e = blockIdx.x * blockDim.x + threadIdx.x;
    if (e < E) {
        int d = ei[E + e];
        int pos = offs[d] + atomicAdd(&cur[d], 1);
        csr[pos] = (unsigned)ei[e] | ((unsigned)et[e] << 16);
    }
}

// ---------------------------------------------------------------------------
// Gather. Layer 1: root(from Y1ext)+bias+messages, relu, fp16 round.
// ---------------------------------------------------------------------------
__global__ void __launch_bounds__(128)
gather1_kernel(const __half* __restrict__ Y,
               const unsigned* __restrict__ csr,
               const int* __restrict__ offs,
               const int* __restrict__ cnt,
               const float* __restrict__ bias,
               __half* __restrict__ h16)
{
    const int dst = blockIdx.x;
    const int tid = threadIdx.x;
    __shared__ float nrm[8];
    if (tid < 8) nrm[tid] = 1.0f / (float)max(cnt[dst * RELS + tid], 1);
    const int s = offs[dst], t = offs[dst + 1];
    __syncthreads();

    float2 bb = *(const float2*)(bias + tid * 2);
    float2 rt = __half22float2(__ldg((const __half2*)(Y + (size_t)dst * 2304 + 2048) + tid));
    float2 acc = make_float2(rt.x + bb.x, rt.y + bb.y);

    int e = s;
    for (; e + 4 <= t; e += 4) {
        unsigned p0 = csr[e], p1 = csr[e + 1], p2 = csr[e + 2], p3 = csr[e + 3];
        __half2 y0 = __ldg((const __half2*)(Y + (size_t)(p0 & 0xFFFFu) * 2304 + (p0 >> 16) * 256) + tid);
        __half2 y1 = __ldg((const __half2*)(Y + (size_t)(p1 & 0xFFFFu) * 2304 + (p1 >> 16) * 256) + tid);
        __half2 y2 = __ldg((const __half2*)(Y + (size_t)(p2 & 0xFFFFu) * 2304 + (p2 >> 16) * 256) + tid);
        __half2 y3 = __ldg((const __half2*)(Y + (size_t)(p3 & 0xFFFFu) * 2304 + (p3 >> 16) * 256) + tid);
        float2 f0 = __half22float2(y0), f1 = __half22float2(y1);
        float2 f2 = __half22float2(y2), f3 = __half22float2(y3);
        float n0 = nrm[p0 >> 16], n1 = nrm[p1 >> 16], n2 = nrm[p2 >> 16], n3 = nrm[p3 >> 16];
        acc.x += f0.x * n0 + f1.x * n1 + f2.x * n2 + f3.x * n3;
        acc.y += f0.y * n0 + f1.y * n1 + f2.y * n2 + f3.y * n3;
    }
    for (; e < t; e++) {
        unsigned p = csr[e];
        __half2 y = __ldg((const __half2*)(Y + (size_t)(p & 0xFFFFu) * 2304 + (p >> 16) * 256) + tid);
        float2 f = __half22float2(y);
        float n = nrm[p >> 16];
        acc.x += f.x * n;
        acc.y += f.y * n;
    }

    acc.x = fmaxf(acc.x, 0.f);
    acc.y = fmaxf(acc.y, 0.f);
    *(__half2*)(h16 + (size_t)dst * 256 + tid * 2) = __floats2half2_rn(acc.x, acc.y);
}

// Layer 2: out = root(from Y2ext) + bias + messages. 64 thr.
__global__ void __launch_bounds__(64)
gather2_kernel(const __half* __restrict__ Y,
               const unsigned* __restrict__ csr,
               const int* __restrict__ offs,
               const int* __restrict__ cnt,
               const float* __restrict__ bias,
               float* __restrict__ out)
{
    const int dst = blockIdx.x;
    const int tid = threadIdx.x;
    __shared__ float nrm[8];
    if (tid < 8) nrm[tid] = 1.0f / (float)max(cnt[dst * RELS + tid], 1);
    const int s = offs[dst], t = offs[dst + 1];
    __syncthreads();

    float2 bb = *(const float2*)(bias + tid * 2);
    float2 rt = __half22float2(__ldg((const __half2*)(Y + (size_t)dst * 1152 + 1024) + tid));
    float2 acc = make_float2(rt.x + bb.x, rt.y + bb.y);

    int e = s;
    for (; e + 4 <= t; e += 4) {
        unsigned p0 = csr[e], p1 = csr[e + 1], p2 = csr[e + 2], p3 = csr[e + 3];
        __half2 y0 = __ldg((const __half2*)(Y + (size_t)(p0 & 0xFFFFu) * 1152 + (p0 >> 16) * 128) + tid);
        __half2 y1 = __ldg((const __half2*)(Y + (size_t)(p1 & 0xFFFFu) * 1152 + (p1 >> 16) * 128) + tid);
        __half2 y2 = __ldg((const __half2*)(Y + (size_t)(p2 & 0xFFFFu) * 1152 + (p2 >> 16) * 128) + tid);
        __half2 y3 = __ldg((const __half2*)(Y + (size_t)(p3 & 0xFFFFu) * 1152 + (p3 >> 16) * 128) + tid);
        float2 f0 = __half22float2(y0), f1 = __half22float2(y1);
        float2 f2 = __half22float2(y2), f3 = __half22float2(y3);
        float n0 = nrm[p0 >> 16], n1 = nrm[p1 >> 16], n2 = nrm[p2 >> 16], n3 = nrm[p3 >> 16];
        acc.x += f0.x * n0 + f1.x * n1 + f2.x * n2 + f3.x * n3;
        acc.y += f0.y * n0 + f1.y * n1 + f2.y * n2 + f3.y * n3;
    }
    for (; e < t; e++) {
        unsigned p = csr[e];
        __half2 y = __ldg((const __half2*)(Y + (size_t)(p & 0xFFFFu) * 1152 + (p >> 16) * 128) + tid);
        float2 f = __half22float2(y);
        float n = nrm[p >> 16];
        acc.x += f.x * n;
        acc.y += f.y * n;
    }
    *(float2*)(out + (size_t)dst * 128 + tid * 2) = acc;
}

// ---------------------------------------------------------------------------
extern "C" void kernel_launch(void* const* d_in, const int* in_sizes, int n_in,
                              void* d_out, int out_size)
{
    const float* x     = (const float*)d_in[0];
    const int*   ei    = (const int*)d_in[1];
    const int*   et    = (const int*)d_in[2];
    const float* W1    = (const float*)d_in[3];
    const float* root1 = (const float*)d_in[4];
    const float* b1    = (const float*)d_in[5];
    const float* W2    = (const float*)d_in[6];
    const float* root2 = (const float*)d_in[7];
    const float* b2    = (const float*)d_in[8];
    float*       out   = (float*)d_out;

    const int N = in_sizes[0] / 256;
    const int E = in_sizes[2];

    __half *Y1, *Y2, *x16, *h16, *w1, *w2;
    int *cnt, *deg, *offs, *cur;
    unsigned* csr;
    cudaGetSymbolAddress((void**)&Y1, g_Y1);
    cudaGetSymbolAddress((void**)&Y2, g_Y2);
    cudaGetSymbolAddress((void**)&cnt, g_cnt);
    cudaGetSymbolAddress((void**)&deg, g_deg);
    cudaGetSymbolAddress((void**)&offs, g_offs);
    cudaGetSymbolAddress((void**)&cur, g_cur);
    cudaGetSymbolAddress((void**)&csr, g_csr);
    cudaGetSymbolAddress((void**)&x16, g_x16);
    cudaGetSymbolAddress((void**)&h16, g_h16);
    cudaGetSymbolAddress((void**)&w1, g_w1);
    cudaGetSymbolAddress((void**)&w2, g_w2);

    static cudaStream_t sCsr = nullptr;
    static cudaEvent_t evFork = nullptr, evCsrDone = nullptr;
    static int attr_set = 0;
    if (!attr_set) {
        cudaFuncSetAttribute(gemm_pipe, cudaFuncAttributeMaxDynamicSharedMemorySize, SMEMP);
        cudaStreamCreateWithFlags(&sCsr, cudaStreamNonBlocking);
        cudaEventCreateWithFlags(&evFork, cudaEventDisableTiming);
        cudaEventCreateWithFlags(&evCsrDone, cudaEventDisableTiming);
        attr_set = 1;
    }

    // ---- fork: CSR build + layer-2 weight prep on side stream ----
    cudaEventRecord(evFork, 0);
    cudaStreamWaitEvent(sCsr, evFork, 0);

    zero_int_kernel<<<(N * RELS + 255) / 256, 256, 0, sCsr>>>(cnt, N * RELS);
    zero_int_kernel<<<(N + 255) / 256, 256, 0, sCsr>>>(cur, N);
    count_kernel<<<(E + 255) / 256, 256, 0, sCsr>>>(ei, et, cnt, E);
    deg_kernel<<<(N + 255) / 256, 256, 0, sCsr>>>(cnt, deg, N);
    scan_kernel<<<1, 1024, 0, sCsr>>>(deg, offs, N);
    fill_kernel<<<(E + 255) / 256, 256, 0, sCsr>>>(ei, et, offs, cur, csr, E);
    convw_kernel<<<(8 * 256 * 128 + 255) / 256, 256, 0, sCsr>>>(W2, w2, 128, 8 * 256 * 128);
    convw_kernel<<<(256 * 128 + 255) / 256, 256, 0, sCsr>>>(root2, w2 + 1024 * 256, 128, 256 * 128);
    cudaEventRecord(evCsrDone, sCsr);

    // main stream: layer-1 weight + input prep
    convw_kernel<<<(8 * 256 * 256 + 255) / 256, 256>>>(W1, w1, 256, 8 * 256 * 256);
    convw_kernel<<<(256 * 256 + 255) / 256, 256>>>(root1, w1 + 2048 * 256, 256, 256 * 256);
    convx_kernel<<<(int)(((size_t)N * 256 + 255) / 256), 256>>>(x, x16, (size_t)N * 256);

    const int mtiles = (N + 255) / 256;

    // ---- layer 1: 18 n-tiles (8 rel x 2 + root x 2) ----
    gemm_pipe<<<dim3(mtiles, 18), 256, SMEMP>>>(x16, N, w1, Y1, 2304);

    // join: gather1 needs the CSR (and GEMM2 the W2 prep, covered by same event)
    cudaStreamWaitEvent(0, evCsrDone, 0);
    gather1_kernel<<<N, 128>>>(Y1, csr, offs, cnt, b1, h16);

    // ---- layer 2: 9 n-tiles (8 rel + root) ----
    gemm_pipe<<<dim3(mtiles, 9), 256, SMEMP>>>(h16, N, w2, Y2, 1152);
    gather2_kernel<<<N, 64>>>(Y2, csr, offs, cnt, b2, out);
}

// round 15
// speedup vs baseline: 1.1004x; 1.1004x over previous
#include <cuda_runtime.h>
#include <cuda_bf16.h>
#include <cuda_fp16.h>
#include <cstdint>

// ============================================================================
// RGCN 2-layer, transform-first. Root GEMM fused as a 9th relation.
// GEMMs: single-pass fp16 mma.sync, CTA 128x128 (4x2 warps of 32x64),
// 2-stage cp.async (R13-proven, 2 CTAs/SM). Messages+root fp16.
// CSR pull aggregation with WARP-PER-DST gathers (no smem/barriers).
// CSR build + W2 prep forked onto a side stream.
// ============================================================================

#define MAXN 50000
#define MAXE 840000
#define RELS 8

__device__ __half g_Y1[(size_t)MAXN * 2304];   // [N, 8*256 + 256(root)]
__device__ __half g_Y2[(size_t)MAXN * 1152];   // [N, 8*128 + 128(root)]
__device__ int    g_cnt[MAXN * RELS];
__device__ int    g_deg[MAXN];
__device__ int    g_offs[MAXN + 1];
__device__ int    g_cur[MAXN];
__device__ unsigned g_csr[MAXE];

__device__ __half g_x16[(size_t)MAXN * 256];
__device__ __half g_h16[(size_t)MAXN * 256];

__device__ __half g_w1[2304 * 256];            // pre-transposed fp16
__device__ __half g_w2[1152 * 256];

// ---------------------------------------------------------------------------
__device__ __forceinline__ void ldsm4(uint32_t* r, uint32_t addr)
{
    asm volatile("ldmatrix.sync.aligned.m8n8.x4.shared.b16 {%0,%1,%2,%3}, [%4];"
                 : "=r"(r[0]), "=r"(r[1]), "=r"(r[2]), "=r"(r[3]) : "r"(addr));
}

__device__ __forceinline__ void mma_f16(float* c, const uint32_t* a, const uint32_t* b)
{
    asm volatile(
        "mma.sync.aligned.m16n8k16.row.col.f32.f16.f16.f32 "
        "{%0,%1,%2,%3}, {%4,%5,%6,%7}, {%8,%9}, {%0,%1,%2,%3};"
        : "+f"(c[0]), "+f"(c[1]), "+f"(c[2]), "+f"(c[3])
        : "r"(a[0]), "r"(a[1]), "r"(a[2]), "r"(a[3]), "r"(b[0]), "r"(b[1]));
}

#define CP_COMMIT() asm volatile("cp.async.commit_group;" ::: "memory")
#define CP_WAIT1()  asm volatile("cp.async.wait_group 1;" ::: "memory")
#define CP_WAIT0()  asm volatile("cp.async.wait_group 0;" ::: "memory")

__device__ __forceinline__ void cp16(uint32_t dst, const void* src, int sz)
{
    asm volatile("cp.async.ca.shared.global [%0], [%1], 16, %2;"
                 :: "r"(dst), "l"(src), "r"(sz));
}

// ---------------------------------------------------------------------------
// Pipelined GEMM (R13 config): C[M,T] = A16[M,256] @ W[T,256]^T, fp16 out.
// CTA 128x128, 8 warps (4x2 of 32x64), kc=32, 2-stage cp.async, 2 syncs/iter.
// smem/stage: 2 operands x 128 rows x 80B = 20480 B. Total 40 KB.
// ---------------------------------------------------------------------------
#define OP_BYTES 10240
#define STG_BYTES 20480
#define SMEMP (2 * STG_BYTES)

__global__ void __launch_bounds__(256)
gemm_pipe(const __half* __restrict__ A16,
          int M,
          const __half* __restrict__ Bw,
          __half* __restrict__ C, int ldc)
{
    extern __shared__ char smem[];
    uint32_t sb0;
    asm("{ .reg .u64 t; cvta.to.shared.u64 t, %1; cvt.u32.u64 %0, t; }"
        : "=r"(sb0) : "l"(smem));

    const int tid  = threadIdx.x;
    const int wid  = tid >> 5;
    const int lane = tid & 31;
    const int wm   = wid >> 1;      // 0..3
    const int wn   = wid & 1;       // 0..1
    const int bm   = blockIdx.x * 128;
    const int bn   = blockIdx.y * 128;

    float acc[2][8][4];
#pragma unroll
    for (int i = 0; i < 2; i++)
#pragma unroll
        for (int j = 0; j < 8; j++)
#pragma unroll
            for (int q = 0; q < 4; q++) acc[i][j][q] = 0.f;

    const int q8 = lane >> 3;
    const int lg = lane & 7;

    auto load_stage = [&](int stage, int k0) {
        uint32_t sb = sb0 + stage * STG_BYTES;
#pragma unroll
        for (int i = 0; i < 4; i++) {
            int op  = i >> 1;
            int idx = (i & 1) * 256 + tid;
            int row = idx >> 2;
            int seg = (idx & 3) * 8;
            const __half* g;
            int grow;
            int sz = 16;
            if (op == 0) { g = A16; grow = bm + row; if (grow >= M) { grow = 0; sz = 0; } }
            else         { g = Bw;  grow = bn + row; }
            cp16(sb + op * OP_BYTES + row * 80 + seg * 2,
                 g + (size_t)grow * 256 + k0 + seg, sz);
        }
        CP_COMMIT();
    };

    load_stage(0, 0);

    for (int kb = 0; kb < 8; kb++) {
        if (kb < 7) load_stage((kb + 1) & 1, (kb + 1) * 32);
        if (kb < 7) CP_WAIT1(); else CP_WAIT0();
        __syncthreads();

        const uint32_t sb = sb0 + (kb & 1) * STG_BYTES;
        const uint32_t sA_b = sb;
        const uint32_t sBw_b = sb + OP_BYTES;

#pragma unroll
        for (int ks = 0; ks < 2; ks++) {
            uint32_t bw[16];
#pragma unroll
            for (int np = 0; np < 4; np++) {
                int nrow = wn * 64 + np * 16 + lg + ((q8 >> 1) ? 8 : 0);
                int bcol = ks * 32 + ((q8 & 1) ? 16 : 0);
                ldsm4(&bw[np * 4], sBw_b + nrow * 80 + bcol);
            }
#pragma unroll
            for (int mt = 0; mt < 2; mt++) {
                int arow = wm * 32 + mt * 16 + lg + ((q8 & 1) ? 8 : 0);
                int acol = ks * 32 + ((q8 >> 1) ? 16 : 0);
                uint32_t ah[4];
                ldsm4(ah, sA_b + arow * 80 + acol);
#pragma unroll
                for (int nt = 0; nt < 8; nt++) mma_f16(acc[mt][nt], ah, &bw[nt * 2]);
            }
        }
        __syncthreads();
    }

#pragma unroll
    for (int mt = 0; mt < 2; mt++) {
#pragma unroll
        for (int nt = 0; nt < 8; nt++) {
            int gr0  = bm + wm * 32 + mt * 16 + (lane >> 2);
            int gcol = bn + wn * 64 + nt * 8 + (lane & 3) * 2;
#pragma unroll
            for (int h = 0; h < 2; h++) {
                int gr = gr0 + h * 8;
                if (gr < M) {
                    *(__half2*)(C + (size_t)gr * ldc + gcol) =
                        __floats2half2_rn(acc[mt][nt][h * 2 + 0], acc[mt][nt][h * 2 + 1]);
                }
            }
        }
    }
}

// ---------------------------------------------------------------------------
// Prep kernels
// ---------------------------------------------------------------------------
__global__ void convw_kernel(const float* __restrict__ W,
                             __half* __restrict__ w, int N, int total)
{
    int idx = blockIdx.x * blockDim.x + threadIdx.x;
    if (idx >= total) return;
    int n = idx % N;
    int k = (idx / N) & 255;
    int r = idx / (N * 256);
    w[((size_t)r * N + n) * 256 + k] = __float2half_rn(W[idx]);
}

__global__ void convx_kernel(const float* __restrict__ X,
                             __half* __restrict__ x16, size_t total)
{
    size_t i = (size_t)blockIdx.x * blockDim.x + threadIdx.x;
    if (i >= total) return;
    x16[i] = __float2half_rn(X[i]);
}

// ---------------------------------------------------------------------------
// CSR construction
// ---------------------------------------------------------------------------
__global__ void zero_int_kernel(int* p, int n)
{
    int i = blockIdx.x * blockDim.x + threadIdx.x;
    if (i < n) p[i] = 0;
}

__global__ void count_kernel(const int* __restrict__ ei,
                             const int* __restrict__ et,
                             int* __restrict__ cnt, int E)
{
    int e = blockIdx.x * blockDim.x + threadIdx.x;
    if (e < E) atomicAdd(&cnt[ei[E + e] * RELS + et[e]], 1);
}

__global__ void deg_kernel(const int* __restrict__ cnt, int* __restrict__ deg, int n)
{
    int i = blockIdx.x * blockDim.x + threadIdx.x;
    if (i < n) {
        int s = 0;
#pragma unroll
        for (int r = 0; r < RELS; r++) s += cnt[i * RELS + r];
        deg[i] = s;
    }
}

__global__ void scan_kernel(const int* __restrict__ deg, int* __restrict__ offs, int n)
{
    __shared__ int buf[1024];
    __shared__ int carry;
    const int tid = threadIdx.x;
    if (tid == 0) carry = 0;
    __syncthreads();
    for (int base = 0; base < n; base += 1024) {
        int i = base + tid;
        int v = (i < n) ? deg[i] : 0;
        buf[tid] = v;
        __syncthreads();
        for (int d = 1; d < 1024; d <<= 1) {
            int t = (tid >= d) ? buf[tid - d] : 0;
            __syncthreads();
            buf[tid] += t;
            __syncthreads();
        }
        if (i < n) offs[i] = carry + buf[tid] - v;
        __syncthreads();
        if (tid == 0) carry += buf[1023];
        __syncthreads();
    }
    if (tid == 0) offs[n] = carry;
}

__global__ void fill_kernel(const int* __restrict__ ei,
                            const int* __restrict__ et,
                            const int* __restrict__ offs,
                            int* __restrict__ cur,
                            unsigned* __restrict__ csr, int E)
{
    int e = blockIdx.x * blockDim.x + threadIdx.x;
    if (e < E) {
        int d = ei[E + e];
        int pos = offs[d] + atomicAdd(&cur[d], 1);
        csr[pos] = (unsigned)ei[e] | ((unsigned)et[e] << 16);
    }
}

// ---------------------------------------------------------------------------
// Warp-per-dst gathers. Layer 1: 256 fp16/row; lane owns 8 elems (uint4).
// ---------------------------------------------------------------------------
__global__ void __launch_bounds__(256)
gather1_kernel(const __half* __restrict__ Y,
               const unsigned* __restrict__ csr,
               const int* __restrict__ offs,
               const int* __restrict__ cnt,
               const float* __restrict__ bias,
               __half* __restrict__ h16, int N)
{
    const int warp = (blockIdx.x * blockDim.x + threadIdx.x) >> 5;
    const int lane = threadIdx.x & 31;
    if (warp >= N) return;
    const int dst = warp;

    float nrmv = 0.f;
    if (lane < 8) nrmv = 1.0f / (float)max(cnt[dst * RELS + lane], 1);

    const int s = offs[dst], t = offs[dst + 1];

    float acc[8];
    {
        uint4 rv = *(const uint4*)(Y + (size_t)dst * 2304 + 2048 + lane * 8);
        float4 b0 = *(const float4*)(bias + lane * 8);
        float4 b1 = *(const float4*)(bias + lane * 8 + 4);
        const __half2* rh = (const __half2*)&rv;
        float2 f;
        f = __half22float2(rh[0]); acc[0] = f.x + b0.x; acc[1] = f.y + b0.y;
        f = __half22float2(rh[1]); acc[2] = f.x + b0.z; acc[3] = f.y + b0.w;
        f = __half22float2(rh[2]); acc[4] = f.x + b1.x; acc[5] = f.y + b1.y;
        f = __half22float2(rh[3]); acc[6] = f.x + b1.z; acc[7] = f.y + b1.w;
    }

    int e = s;
    for (; e + 4 <= t; e += 4) {
        unsigned p[4];
#pragma unroll
        for (int j = 0; j < 4; j++) p[j] = csr[e + j];
        uint4 v[4];
#pragma unroll
        for (int j = 0; j < 4; j++)
            v[j] = __ldg((const uint4*)(Y + (size_t)(p[j] & 0xFFFFu) * 2304
                                          + (p[j] >> 16) * 256 + lane * 8));
#pragma unroll
        for (int j = 0; j < 4; j++) {
            float n = __shfl_sync(0xFFFFFFFFu, nrmv, (int)(p[j] >> 16));
            const __half2* h = (const __half2*)&v[j];
#pragma unroll
            for (int q = 0; q < 4; q++) {
                float2 ff = __half22float2(h[q]);
                acc[q * 2]     += ff.x * n;
                acc[q * 2 + 1] += ff.y * n;
            }
        }
    }
    for (; e < t; e++) {
        unsigned p = csr[e];
        uint4 v = __ldg((const uint4*)(Y + (size_t)(p & 0xFFFFu) * 2304
                                         + (p >> 16) * 256 + lane * 8));
        float n = __shfl_sync(0xFFFFFFFFu, nrmv, (int)(p >> 16));
        const __half2* h = (const __half2*)&v;
#pragma unroll
        for (int q = 0; q < 4; q++) {
            float2 ff = __half22float2(h[q]);
            acc[q * 2]     += ff.x * n;
            acc[q * 2 + 1] += ff.y * n;
        }
    }

    uint4 ov;
    __half2* oh = (__half2*)&ov;
#pragma unroll
    for (int q = 0; q < 4; q++)
        oh[q] = __floats2half2_rn(fmaxf(acc[q * 2], 0.f), fmaxf(acc[q * 2 + 1], 0.f));
    *(uint4*)(h16 + (size_t)dst * 256 + lane * 8) = ov;
}

// Layer 2: 128 fp16/row; lane owns 4 elems (uint2). fp32 out.
__global__ void __launch_bounds__(256)
gather2_kernel(const __half* __restrict__ Y,
               const unsigned* __restrict__ csr,
               const int* __restrict__ offs,
               const int* __restrict__ cnt,
               const float* __restrict__ bias,
               float* __restrict__ out, int N)
{
    const int warp = (blockIdx.x * blockDim.x + threadIdx.x) >> 5;
    const int lane = threadIdx.x & 31;
    if (warp >= N) return;
    const int dst = warp;

    float nrmv = 0.f;
    if (lane < 8) nrmv = 1.0f / (float)max(cnt[dst * RELS + lane], 1);

    const int s = offs[dst], t = offs[dst + 1];

    float acc[4];
    {
        uint2 rv = *(const uint2*)(Y + (size_t)dst * 1152 + 1024 + lane * 4);
        float4 b0 = *(const float4*)(bias + lane * 4);
        const __half2* rh = (const __half2*)&rv;
        float2 f;
        f = __half22float2(rh[0]); acc[0] = f.x + b0.x; acc[1] = f.y + b0.y;
        f = __half22float2(rh[1]); acc[2] = f.x + b0.z; acc[3] = f.y + b0.w;
    }

    int e = s;
    for (; e + 4 <= t; e += 4) {
        unsigned p[4];
#pragma unroll
        for (int j = 0; j < 4; j++) p[j] = csr[e + j];
        uint2 v[4];
#pragma unroll
        for (int j = 0; j < 4; j++)
            v[j] = __ldg((const uint2*)(Y + (size_t)(p[j] & 0xFFFFu) * 1152
                                          + (p[j] >> 16) * 128 + lane * 4));
#pragma unroll
        for (int j = 0; j < 4; j++) {
            float n = __shfl_sync(0xFFFFFFFFu, nrmv, (int)(p[j] >> 16));
            const __half2* h = (const __half2*)&v[j];
#pragma unroll
            for (int q = 0; q < 2; q++) {
                float2 ff = __half22float2(h[q]);
                acc[q * 2]     += ff.x * n;
                acc[q * 2 + 1] += ff.y * n;
            }
        }
    }
    for (; e < t; e++) {
        unsigned p = csr[e];
        uint2 v = __ldg((const uint2*)(Y + (size_t)(p & 0xFFFFu) * 1152
                                         + (p >> 16) * 128 + lane * 4));
        float n = __shfl_sync(0xFFFFFFFFu, nrmv, (int)(p >> 16));
        const __half2* h = (const __half2*)&v;
#pragma unroll
        for (int q = 0; q < 2; q++) {
            float2 ff = __half22float2(h[q]);
            acc[q * 2]     += ff.x * n;
            acc[q * 2 + 1] += ff.y * n;
        }
    }

    *(float4*)(out + (size_t)dst * 128 + lane * 4) =
        make_float4(acc[0], acc[1], acc[2], acc[3]);
}

// ---------------------------------------------------------------------------
extern "C" void kernel_launch(void* const* d_in, const int* in_sizes, int n_in,
                              void* d_out, int out_size)
{
    const float* x     = (const float*)d_in[0];
    const int*   ei    = (const int*)d_in[1];
    const int*   et    = (const int*)d_in[2];
    const float* W1    = (const float*)d_in[3];
    const float* root1 = (const float*)d_in[4];
    const float* b1    = (const float*)d_in[5];
    const float* W2    = (const float*)d_in[6];
    const float* root2 = (const float*)d_in[7];
    const float* b2    = (const float*)d_in[8];
    float*       out   = (float*)d_out;

    const int N = in_sizes[0] / 256;
    const int E = in_sizes[2];

    __half *Y1, *Y2, *x16, *h16, *w1, *w2;
    int *cnt, *deg, *offs, *cur;
    unsigned* csr;
    cudaGetSymbolAddress((void**)&Y1, g_Y1);
    cudaGetSymbolAddress((void**)&Y2, g_Y2);
    cudaGetSymbolAddress((void**)&cnt, g_cnt);
    cudaGetSymbolAddress((void**)&deg, g_deg);
    cudaGetSymbolAddress((void**)&offs, g_offs);
    cudaGetSymbolAddress((void**)&cur, g_cur);
    cudaGetSymbolAddress((void**)&csr, g_csr);
    cudaGetSymbolAddress((void**)&x16, g_x16);
    cudaGetSymbolAddress((void**)&h16, g_h16);
    cudaGetSymbolAddress((void**)&w1, g_w1);
    cudaGetSymbolAddress((void**)&w2, g_w2);

    static cudaStream_t sCsr = nullptr;
    static cudaEvent_t evFork = nullptr, evCsrDone = nullptr;
    static int attr_set = 0;
    if (!attr_set) {
        cudaFuncSetAttribute(gemm_pipe, cudaFuncAttributeMaxDynamicSharedMemorySize, SMEMP);
        cudaStreamCreateWithFlags(&sCsr, cudaStreamNonBlocking);
        cudaEventCreateWithFlags(&evFork, cudaEventDisableTiming);
        cudaEventCreateWithFlags(&evCsrDone, cudaEventDisableTiming);
        attr_set = 1;
    }

    // ---- fork: CSR build + layer-2 weight prep on side stream ----
    cudaEventRecord(evFork, 0);
    cudaStreamWaitEvent(sCsr, evFork, 0);

    zero_int_kernel<<<(N * RELS + 255) / 256, 256, 0, sCsr>>>(cnt, N * RELS);
    zero_int_kernel<<<(N + 255) / 256, 256, 0, sCsr>>>(cur, N);
    count_kernel<<<(E + 255) / 256, 256, 0, sCsr>>>(ei, et, cnt, E);
    deg_kernel<<<(N + 255) / 256, 256, 0, sCsr>>>(cnt, deg, N);
    scan_kernel<<<1, 1024, 0, sCsr>>>(deg, offs, N);
    fill_kernel<<<(E + 255) / 256, 256, 0, sCsr>>>(ei, et, offs, cur, csr, E);
    convw_kernel<<<(8 * 256 * 128 + 255) / 256, 256, 0, sCsr>>>(W2, w2, 128, 8 * 256 * 128);
    convw_kernel<<<(256 * 128 + 255) / 256, 256, 0, sCsr>>>(root2, w2 + 1024 * 256, 128, 256 * 128);
    cudaEventRecord(evCsrDone, sCsr);

    // main stream: layer-1 weight + input prep
    convw_kernel<<<(8 * 256 * 256 + 255) / 256, 256>>>(W1, w1, 256, 8 * 256 * 256);
    convw_kernel<<<(256 * 256 + 255) / 256, 256>>>(root1, w1 + 2048 * 256, 256, 256 * 256);
    convx_kernel<<<(int)(((size_t)N * 256 + 255) / 256), 256>>>(x, x16, (size_t)N * 256);

    const int mtiles = (N + 127) / 128;

    // ---- layer 1: 18 n-tiles (8 rel x 2 + root x 2) ----
    gemm_pipe<<<dim3(mtiles, 18), 256, SMEMP>>>(x16, N, w1, Y1, 2304);

    // join: gather1 needs the CSR (and GEMM2 the W2 prep, covered by same event)
    cudaStreamWaitEvent(0, evCsrDone, 0);
    gather1_kernel<<<(N + 7) / 8, 256>>>(Y1, csr, offs, cnt, b1, h16, N);

    // ---- layer 2: 9 n-tiles (8 rel + root) ----
    gemm_pipe<<<dim3(mtiles, 9), 256, SMEMP>>>(h16, N, w2, Y2, 1152);
    gather2_kernel<<<(N + 7) / 8, 256>>>(Y2, csr, offs, cnt, b2, out, N);
}

// round 16
// speedup vs baseline: 1.1397x; 1.0357x over previous
#include <cuda_runtime.h>
#include <cuda_bf16.h>
#include <cuda_fp16.h>
#include <cstdint>

// ============================================================================
// RGCN 2-layer, transform-first. Root GEMM fused as a 9th relation.
// GEMMs: single-pass fp16 mma.sync, CTA 128x128 (4x2 warps of 32x64),
// kc=64 (two 32-k sub-blocks per stage), 2-stage cp.async, 2 CTAs/SM.
// Messages+root fp16. Warp-per-dst CSR pull gathers.
// CSR build + W2 prep forked onto a side stream.
// ============================================================================

#define MAXN 50000
#define MAXE 840000
#define RELS 8

__device__ __half g_Y1[(size_t)MAXN * 2304];   // [N, 8*256 + 256(root)]
__device__ __half g_Y2[(size_t)MAXN * 1152];   // [N, 8*128 + 128(root)]
__device__ int    g_cnt[MAXN * RELS];
__device__ int    g_deg[MAXN];
__device__ int    g_offs[MAXN + 1];
__device__ int    g_cur[MAXN];
__device__ unsigned g_csr[MAXE];

__device__ __half g_x16[(size_t)MAXN * 256];
__device__ __half g_h16[(size_t)MAXN * 256];

__device__ __half g_w1[2304 * 256];            // pre-transposed fp16
__device__ __half g_w2[1152 * 256];

// ---------------------------------------------------------------------------
__device__ __forceinline__ void ldsm4(uint32_t* r, uint32_t addr)
{
    asm volatile("ldmatrix.sync.aligned.m8n8.x4.shared.b16 {%0,%1,%2,%3}, [%4];"
                 : "=r"(r[0]), "=r"(r[1]), "=r"(r[2]), "=r"(r[3]) : "r"(addr));
}

__device__ __forceinline__ void mma_f16(float* c, const uint32_t* a, const uint32_t* b)
{
    asm volatile(
        "mma.sync.aligned.m16n8k16.row.col.f32.f16.f16.f32 "
        "{%0,%1,%2,%3}, {%4,%5,%6,%7}, {%8,%9}, {%0,%1,%2,%3};"
        : "+f"(c[0]), "+f"(c[1]), "+f"(c[2]), "+f"(c[3])
        : "r"(a[0]), "r"(a[1]), "r"(a[2]), "r"(a[3]), "r"(b[0]), "r"(b[1]));
}

#define CP_COMMIT() asm volatile("cp.async.commit_group;" ::: "memory")
#define CP_WAIT1()  asm volatile("cp.async.wait_group 1;" ::: "memory")
#define CP_WAIT0()  asm volatile("cp.async.wait_group 0;" ::: "memory")

__device__ __forceinline__ void cp16(uint32_t dst, const void* src, int sz)
{
    asm volatile("cp.async.ca.shared.global [%0], [%1], 16, %2;"
                 :: "r"(dst), "l"(src), "r"(sz));
}

// ---------------------------------------------------------------------------
// Pipelined GEMM: C[M,T] = A16[M,256] @ W[T,256]^T, fp16 out.
// CTA 128x128, 8 warps (4x2 of 32x64), kc=64 (2 sub-blocks of 32),
// 2-stage cp.async. smem/stage: 4 sub-bufs x 128x80B = 40960 B. Total 80 KB.
// ---------------------------------------------------------------------------
#define SUB_BYTES 10240
#define STG_BYTES 40960
#define SMEMP (2 * STG_BYTES)

__global__ void __launch_bounds__(256)
gemm_pipe(const __half* __restrict__ A16,
          int M,
          const __half* __restrict__ Bw,
          __half* __restrict__ C, int ldc)
{
    extern __shared__ char smem[];
    uint32_t sb0;
    asm("{ .reg .u64 t; cvta.to.shared.u64 t, %1; cvt.u32.u64 %0, t; }"
        : "=r"(sb0) : "l"(smem));

    const int tid  = threadIdx.x;
    const int wid  = tid >> 5;
    const int lane = tid & 31;
    const int wm   = wid >> 1;      // 0..3
    const int wn   = wid & 1;       // 0..1
    const int bm   = blockIdx.x * 128;
    const int bn   = blockIdx.y * 128;

    float acc[2][8][4];
#pragma unroll
    for (int i = 0; i < 2; i++)
#pragma unroll
        for (int j = 0; j < 8; j++)
#pragma unroll
            for (int q = 0; q < 4; q++) acc[i][j][q] = 0.f;

    const int q8 = lane >> 3;
    const int lg = lane & 7;

    // stage layout: [A k0..31 | A k32..63 | B k0..31 | B k32..63], 80B pitch
    auto load_stage = [&](int stage, int k0) {
        uint32_t sb = sb0 + stage * STG_BYTES;
#pragma unroll
        for (int i = 0; i < 8; i++) {
            int c    = i * 256 + tid;        // 0..2047
            int sub  = c >> 9;               // 0..3
            int idx  = c & 511;
            int row  = idx >> 2;
            int seg  = (idx & 3) * 8;
            int op   = sub >> 1;             // 0=A, 1=B
            int koff = (sub & 1) * 32;
            int sz = 16;
            const __half* g;
            int grow;
            if (op == 0) { g = A16; grow = bm + row; if (grow >= M) { grow = 0; sz = 0; } }
            else         { g = Bw;  grow = bn + row; }
            cp16(sb + sub * SUB_BYTES + row * 80 + seg * 2,
                 g + (size_t)grow * 256 + k0 + koff + seg, sz);
        }
        CP_COMMIT();
    };

    load_stage(0, 0);

    for (int kb = 0; kb < 4; kb++) {
        if (kb < 3) load_stage((kb + 1) & 1, (kb + 1) * 64);
        if (kb < 3) CP_WAIT1(); else CP_WAIT0();
        __syncthreads();

        const uint32_t sb = sb0 + (kb & 1) * STG_BYTES;

#pragma unroll
        for (int ks = 0; ks < 4; ks++) {
            const uint32_t sA_b  = sb + (ks >> 1) * SUB_BYTES;
            const uint32_t sBw_b = sb + 2 * SUB_BYTES + (ks >> 1) * SUB_BYTES;
            const int kcol = (ks & 1) * 32;

            uint32_t bw[16];
#pragma unroll
            for (int np = 0; np < 4; np++) {
                int nrow = wn * 64 + np * 16 + lg + ((q8 >> 1) ? 8 : 0);
                int bcol = kcol + ((q8 & 1) ? 16 : 0);
                ldsm4(&bw[np * 4], sBw_b + nrow * 80 + bcol);
            }
#pragma unroll
            for (int mt = 0; mt < 2; mt++) {
                int arow = wm * 32 + mt * 16 + lg + ((q8 & 1) ? 8 : 0);
                int acol = kcol + ((q8 >> 1) ? 16 : 0);
                uint32_t ah[4];
                ldsm4(ah, sA_b + arow * 80 + acol);
#pragma unroll
                for (int nt = 0; nt < 8; nt++) mma_f16(acc[mt][nt], ah, &bw[nt * 2]);
            }
        }
        __syncthreads();
    }

#pragma unroll
    for (int mt = 0; mt < 2; mt++) {
#pragma unroll
        for (int nt = 0; nt < 8; nt++) {
            int gr0  = bm + wm * 32 + mt * 16 + (lane >> 2);
            int gcol = bn + wn * 64 + nt * 8 + (lane & 3) * 2;
#pragma unroll
            for (int h = 0; h < 2; h++) {
                int gr = gr0 + h * 8;
                if (gr < M) {
                    *(__half2*)(C + (size_t)gr * ldc + gcol) =
                        __floats2half2_rn(acc[mt][nt][h * 2 + 0], acc[mt][nt][h * 2 + 1]);
                }
            }
        }
    }
}

// ---------------------------------------------------------------------------
// Prep kernels
// ---------------------------------------------------------------------------
__global__ void convw_kernel(const float* __restrict__ W,
                             __half* __restrict__ w, int N, int total)
{
    int idx = blockIdx.x * blockDim.x + threadIdx.x;
    if (idx >= total) return;
    int n = idx % N;
    int k = (idx / N) & 255;
    int r = idx / (N * 256);
    w[((size_t)r * N + n) * 256 + k] = __float2half_rn(W[idx]);
}

__global__ void convx_kernel(const float* __restrict__ X,
                             __half* __restrict__ x16, size_t total)
{
    size_t i = (size_t)blockIdx.x * blockDim.x + threadIdx.x;
    if (i >= total) return;
    x16[i] = __float2half_rn(X[i]);
}

// ---------------------------------------------------------------------------
// CSR construction
// ---------------------------------------------------------------------------
__global__ void zero_int_kernel(int* p, int n)
{
    int i = blockIdx.x * blockDim.x + threadIdx.x;
    if (i < n) p[i] = 0;
}

__global__ void count_kernel(const int* __restrict__ ei,
                             const int* __restrict__ et,
                             int* __restrict__ cnt, int E)
{
    int e = blockIdx.x * blockDim.x + threadIdx.x;
    if (e < E) atomicAdd(&cnt[ei[E + e] * RELS + et[e]], 1);
}

__global__ void deg_kernel(const int* __restrict__ cnt, int* __restrict__ deg, int n)
{
    int i = blockIdx.x * blockDim.x + threadIdx.x;
    if (i < n) {
        int s = 0;
#pragma unroll
        for (int r = 0; r < RELS; r++) s += cnt[i * RELS + r];
        deg[i] = s;
    }
}

__global__ void scan_kernel(const int* __restrict__ deg, int* __restrict__ offs, int n)
{
    __shared__ int buf[1024];
    __shared__ int carry;
    const int tid = threadIdx.x;
    if (tid == 0) carry = 0;
    __syncthreads();
    for (int base = 0; base < n; base += 1024) {
        int i = base + tid;
        int v = (i < n) ? deg[i] : 0;
        buf[tid] = v;
        __syncthreads();
        for (int d = 1; d < 1024; d <<= 1) {
            int t = (tid >= d) ? buf[tid - d] : 0;
            __syncthreads();
            buf[tid] += t;
            __syncthreads();
        }
        if (i < n) offs[i] = carry + buf[tid] - v;
        __syncthreads();
        if (tid == 0) carry += buf[1023];
        __syncthreads();
    }
    if (tid == 0) offs[n] = carry;
}

__global__ void fill_kernel(const int* __restrict__ ei,
                            const int* __restrict__ et,
                            const int* __restrict__ offs,
                            int* __restrict__ cur,
                            unsigned* __restrict__ csr, int E)
{
    int e = blockIdx.x * blockDim.x + threadIdx.x;
    if (e < E) {
        int d = ei[E + e];
        int pos = offs[d] + atomicAdd(&cur[d], 1);
        csr[pos] = (unsigned)ei[e] | ((unsigned)et[e] << 16);
    }
}

// ---------------------------------------------------------------------------
// Warp-per-dst gathers. Layer 1: 256 fp16/row; lane owns 8 elems (uint4).
// ---------------------------------------------------------------------------
__global__ void __launch_bounds__(256)
gather1_kernel(const __half* __restrict__ Y,
               const unsigned* __restrict__ csr,
               const int* __restrict__ offs,
               const int* __restrict__ cnt,
               const float* __restrict__ bias,
               __half* __restrict__ h16, int N)
{
    const int warp = (blockIdx.x * blockDim.x + threadIdx.x) >> 5;
    const int lane = threadIdx.x & 31;
    if (warp >= N) return;
    const int dst = warp;

    float nrmv = 0.f;
    if (lane < 8) nrmv = 1.0f / (float)max(cnt[dst * RELS + lane], 1);

    const int s = offs[dst], t = offs[dst + 1];

    float acc[8];
    {
        uint4 rv = *(const uint4*)(Y + (size_t)dst * 2304 + 2048 + lane * 8);
        float4 b0 = *(const float4*)(bias + lane * 8);
        float4 b1 = *(const float4*)(bias + lane * 8 + 4);
        const __half2* rh = (const __half2*)&rv;
        float2 f;
        f = __half22float2(rh[0]); acc[0] = f.x + b0.x; acc[1] = f.y + b0.y;
        f = __half22float2(rh[1]); acc[2] = f.x + b0.z; acc[3] = f.y + b0.w;
        f = __half22float2(rh[2]); acc[4] = f.x + b1.x; acc[5] = f.y + b1.y;
        f = __half22float2(rh[3]); acc[6] = f.x + b1.z; acc[7] = f.y + b1.w;
    }

    int e = s;
    for (; e + 4 <= t; e += 4) {
        unsigned p[4];
#pragma unroll
        for (int j = 0; j < 4; j++) p[j] = csr[e + j];
        uint4 v[4];
#pragma unroll
        for (int j = 0; j < 4; j++)
            v[j] = __ldg((const uint4*)(Y + (size_t)(p[j] & 0xFFFFu) * 2304
                                          + (p[j] >> 16) * 256 + lane * 8));
#pragma unroll
        for (int j = 0; j < 4; j++) {
            float n = __shfl_sync(0xFFFFFFFFu, nrmv, (int)(p[j] >> 16));
            const __half2* h = (const __half2*)&v[j];
#pragma unroll
            for (int q = 0; q < 4; q++) {
                float2 ff = __half22float2(h[q]);
                acc[q * 2]     += ff.x * n;
                acc[q * 2 + 1] += ff.y * n;
            }
        }
    }
    for (; e < t; e++) {
        unsigned p = csr[e];
        uint4 v = __ldg((const uint4*)(Y + (size_t)(p & 0xFFFFu) * 2304
                                         + (p >> 16) * 256 + lane * 8));
        float n = __shfl_sync(0xFFFFFFFFu, nrmv, (int)(p >> 16));
        const __half2* h = (const __half2*)&v;
#pragma unroll
        for (int q = 0; q < 4; q++) {
            float2 ff = __half22float2(h[q]);
            acc[q * 2]     += ff.x * n;
            acc[q * 2 + 1] += ff.y * n;
        }
    }

    uint4 ov;
    __half2* oh = (__half2*)&ov;
#pragma unroll
    for (int q = 0; q < 4; q++)
        oh[q] = __floats2half2_rn(fmaxf(acc[q * 2], 0.f), fmaxf(acc[q * 2 + 1], 0.f));
    *(uint4*)(h16 + (size_t)dst * 256 + lane * 8) = ov;
}

// Layer 2: 128 fp16/row; lane owns 4 elems (uint2). fp32 out.
__global__ void __launch_bounds__(256)
gather2_kernel(const __half* __restrict__ Y,
               const unsigned* __restrict__ csr,
               const int* __restrict__ offs,
               const int* __restrict__ cnt,
               const float* __restrict__ bias,
               float* __restrict__ out, int N)
{
    const int warp = (blockIdx.x * blockDim.x + threadIdx.x) >> 5;
    const int lane = threadIdx.x & 31;
    if (warp >= N) return;
    const int dst = warp;

    float nrmv = 0.f;
    if (lane < 8) nrmv = 1.0f / (float)max(cnt[dst * RELS + lane], 1);

    const int s = offs[dst], t = offs[dst + 1];

    float acc[4];
    {
        uint2 rv = *(const uint2*)(Y + (size_t)dst * 1152 + 1024 + lane * 4);
        float4 b0 = *(const float4*)(bias + lane * 4);
        const __half2* rh = (const __half2*)&rv;
        float2 f;
        f = __half22float2(rh[0]); acc[0] = f.x + b0.x; acc[1] = f.y + b0.y;
        f = __half22float2(rh[1]); acc[2] = f.x + b0.z; acc[3] = f.y + b0.w;
    }

    int e = s;
    for (; e + 4 <= t; e += 4) {
        unsigned p[4];
#pragma unroll
        for (int j = 0; j < 4; j++) p[j] = csr[e + j];
        uint2 v[4];
#pragma unroll
        for (int j = 0; j < 4; j++)
            v[j] = __ldg((const uint2*)(Y + (size_t)(p[j] & 0xFFFFu) * 1152
                                          + (p[j] >> 16) * 128 + lane * 4));
#pragma unroll
        for (int j = 0; j < 4; j++) {
            float n = __shfl_sync(0xFFFFFFFFu, nrmv, (int)(p[j] >> 16));
            const __half2* h = (const __half2*)&v[j];
#pragma unroll
            for (int q = 0; q < 2; q++) {
                float2 ff = __half22float2(h[q]);
                acc[q * 2]     += ff.x * n;
                acc[q * 2 + 1] += ff.y * n;
            }
        }
    }
    for (; e < t; e++) {
        unsigned p = csr[e];
        uint2 v = __ldg((const uint2*)(Y + (size_t)(p & 0xFFFFu) * 1152
                                         + (p >> 16) * 128 + lane * 4));
        float n = __shfl_sync(0xFFFFFFFFu, nrmv, (int)(p >> 16));
        const __half2* h = (const __half2*)&v;
#pragma unroll
        for (int q = 0; q < 2; q++) {
            float2 ff = __half22float2(h[q]);
            acc[q * 2]     += ff.x * n;
            acc[q * 2 + 1] += ff.y * n;
        }
    }

    *(float4*)(out + (size_t)dst * 128 + lane * 4) =
        make_float4(acc[0], acc[1], acc[2], acc[3]);
}

// ---------------------------------------------------------------------------
extern "C" void kernel_launch(void* const* d_in, const int* in_sizes, int n_in,
                              void* d_out, int out_size)
{
    const float* x     = (const float*)d_in[0];
    const int*   ei    = (const int*)d_in[1];
    const int*   et    = (const int*)d_in[2];
    const float* W1    = (const float*)d_in[3];
    const float* root1 = (const float*)d_in[4];
    const float* b1    = (const float*)d_in[5];
    const float* W2    = (const float*)d_in[6];
    const float* root2 = (const float*)d_in[7];
    const float* b2    = (const float*)d_in[8];
    float*       out   = (float*)d_out;

    const int N = in_sizes[0] / 256;
    const int E = in_sizes[2];

    __half *Y1, *Y2, *x16, *h16, *w1, *w2;
    int *cnt, *deg, *offs, *cur;
    unsigned* csr;
    cudaGetSymbolAddress((void**)&Y1, g_Y1);
    cudaGetSymbolAddress((void**)&Y2, g_Y2);
    cudaGetSymbolAddress((void**)&cnt, g_cnt);
    cudaGetSymbolAddress((void**)&deg, g_deg);
    cudaGetSymbolAddress((void**)&offs, g_offs);
    cudaGetSymbolAddress((void**)&cur, g_cur);
    cudaGetSymbolAddress((void**)&csr, g_csr);
    cudaGetSymbolAddress((void**)&x16, g_x16);
    cudaGetSymbolAddress((void**)&h16, g_h16);
    cudaGetSymbolAddress((void**)&w1, g_w1);
    cudaGetSymbolAddress((void**)&w2, g_w2);

    static cudaStream_t sCsr = nullptr;
    static cudaEvent_t evFork = nullptr, evCsrDone = nullptr;
    static int attr_set = 0;
    if (!attr_set) {
        cudaFuncSetAttribute(gemm_pipe, cudaFuncAttributeMaxDynamicSharedMemorySize, SMEMP);
        cudaStreamCreateWithFlags(&sCsr, cudaStreamNonBlocking);
        cudaEventCreateWithFlags(&evFork, cudaEventDisableTiming);
        cudaEventCreateWithFlags(&evCsrDone, cudaEventDisableTiming);
        attr_set = 1;
    }

    // ---- fork: CSR build + layer-2 weight prep on side stream ----
    cudaEventRecord(evFork, 0);
    cudaStreamWaitEvent(sCsr, evFork, 0);

    zero_int_kernel<<<(N * RELS + 255) / 256, 256, 0, sCsr>>>(cnt, N * RELS);
    zero_int_kernel<<<(N + 255) / 256, 256, 0, sCsr>>>(cur, N);
    count_kernel<<<(E + 255) / 256, 256, 0, sCsr>>>(ei, et, cnt, E);
    deg_kernel<<<(N + 255) / 256, 256, 0, sCsr>>>(cnt, deg, N);
    scan_kernel<<<1, 1024, 0, sCsr>>>(deg, offs, N);
    fill_kernel<<<(E + 255) / 256, 256, 0, sCsr>>>(ei, et, offs, cur, csr, E);
    convw_kernel<<<(8 * 256 * 128 + 255) / 256, 256, 0, sCsr>>>(W2, w2, 128, 8 * 256 * 128);
    convw_kernel<<<(256 * 128 + 255) / 256, 256, 0, sCsr>>>(root2, w2 + 1024 * 256, 128, 256 * 128);
    cudaEventRecord(evCsrDone, sCsr);

    // main stream: layer-1 weight + input prep
    convw_kernel<<<(8 * 256 * 256 + 255) / 256, 256>>>(W1, w1, 256, 8 * 256 * 256);
    convw_kernel<<<(256 * 256 + 255) / 256, 256>>>(root1, w1 + 2048 * 256, 256, 256 * 256);
    convx_kernel<<<(int)(((size_t)N * 256 + 255) / 256), 256>>>(x, x16, (size_t)N * 256);

    const int mtiles = (N + 127) / 128;

    // ---- layer 1: 18 n-tiles (8 rel x 2 + root x 2) ----
    gemm_pipe<<<dim3(mtiles, 18), 256, SMEMP>>>(x16, N, w1, Y1, 2304);

    // join: gather1 needs the CSR (and GEMM2 the W2 prep, covered by same event)
    cudaStreamWaitEvent(0, evCsrDone, 0);
    gather1_kernel<<<(N + 7) / 8, 256>>>(Y1, csr, offs, cnt, b1, h16, N);

    // ---- layer 2: 9 n-tiles (8 rel + root) ----
    gemm_pipe<<<dim3(mtiles, 9), 256, SMEMP>>>(h16, N, w2, Y2, 1152);
    gather2_kernel<<<(N + 7) / 8, 256>>>(Y2, csr, offs, cnt, b2, out, N);
}